// round 1
// baseline (speedup 1.0000x reference)
#include <cuda_runtime.h>
#include <math.h>

#define NUM_TOKENS 16384
#define NUM_EXPERTS 256
#define HIDDEN 7168

#define BM 64
#define BN 256
#define BK 16
#define NTHREADS 256

typedef unsigned long long ull;

// Scratch for gate logits [T, E] fp32 (device-global: no allocation allowed)
__device__ float g_logits[NUM_TOKENS * NUM_EXPERTS];

// ---------------------------------------------------------------------------
// f32x2 packed-math helpers (SASS FFMA2 — only reachable via PTX fma.rn.f32x2)
// ---------------------------------------------------------------------------
__device__ __forceinline__ void fma2(ull& acc, ull a, ull b) {
    asm("fma.rn.f32x2 %0, %1, %2, %0;" : "+l"(acc) : "l"(a), "l"(b));
}
__device__ __forceinline__ ull pack2(float x, float y) {
    ull r; asm("mov.b64 %0, {%1, %2};" : "=l"(r) : "f"(x), "f"(y)); return r;
}
__device__ __forceinline__ float2 unpack2(ull v) {
    float2 f; asm("mov.b64 {%0, %1}, %2;" : "=f"(f.x), "=f"(f.y) : "l"(v)); return f;
}

// ---------------------------------------------------------------------------
// Kernel 1: logits = H @ W^T   (fp32, f32x2 packed FMA)
// grid = T/BM = 256 blocks, 256 threads
// Thread tile: rows {ty*4+0..3, ty*4+32..35}, cols {tx*4+0..3, tx*4+128..131}
// Accumulators pair adjacent ROWS into f32x2 (a-pairs come packed for free
// from the float4 shared load; only b needs a {b,b} broadcast pack).
// ---------------------------------------------------------------------------
__global__ __launch_bounds__(NTHREADS, 2)
void gate_gemm_kernel(const float* __restrict__ A, const float* __restrict__ W) {
    __shared__ float As[BK][BM + 4];   // transposed A tile, padded stride 68
    __shared__ float Bs[BK][BN];       // transposed W tile

    const int tid = threadIdx.x;
    const int tx  = tid & 31;          // 0..31 -> column groups
    const int ty  = tid >> 5;          // 0..7  -> row groups
    const int block_m = blockIdx.x * BM;

    // Global load assignment
    const int aRow = tid >> 2;          // 0..63
    const int aK   = (tid & 3) * 4;     // 0,4,8,12
    const float* Aptr = A + (size_t)(block_m + aRow) * HIDDEN + aK;
    const float* Wptr = W + (size_t)tid * HIDDEN;   // one expert row per thread

    ull acc[4][8];
#pragma unroll
    for (int i = 0; i < 4; i++)
#pragma unroll
        for (int j = 0; j < 8; j++) acc[i][j] = 0ull;

    // Prefetch first tile into registers
    float4 aReg  = *reinterpret_cast<const float4*>(Aptr);
    float4 bReg0 = *reinterpret_cast<const float4*>(Wptr + 0);
    float4 bReg1 = *reinterpret_cast<const float4*>(Wptr + 4);
    float4 bReg2 = *reinterpret_cast<const float4*>(Wptr + 8);
    float4 bReg3 = *reinterpret_cast<const float4*>(Wptr + 12);

    const int KT = HIDDEN / BK;  // 448
    for (int kt = 0; kt < KT; kt++) {
        __syncthreads();
        // Store prefetched tile (transposed)
        As[aK + 0][aRow] = aReg.x;
        As[aK + 1][aRow] = aReg.y;
        As[aK + 2][aRow] = aReg.z;
        As[aK + 3][aRow] = aReg.w;
        Bs[ 0][tid] = bReg0.x; Bs[ 1][tid] = bReg0.y; Bs[ 2][tid] = bReg0.z; Bs[ 3][tid] = bReg0.w;
        Bs[ 4][tid] = bReg1.x; Bs[ 5][tid] = bReg1.y; Bs[ 6][tid] = bReg1.z; Bs[ 7][tid] = bReg1.w;
        Bs[ 8][tid] = bReg2.x; Bs[ 9][tid] = bReg2.y; Bs[10][tid] = bReg2.z; Bs[11][tid] = bReg2.w;
        Bs[12][tid] = bReg3.x; Bs[13][tid] = bReg3.y; Bs[14][tid] = bReg3.z; Bs[15][tid] = bReg3.w;
        __syncthreads();

        // Prefetch next tile (overlaps with compute below)
        if (kt + 1 < KT) {
            const float* ap = Aptr + (size_t)(kt + 1) * BK;
            const float* wp = Wptr + (size_t)(kt + 1) * BK;
            aReg  = *reinterpret_cast<const float4*>(ap);
            bReg0 = *reinterpret_cast<const float4*>(wp + 0);
            bReg1 = *reinterpret_cast<const float4*>(wp + 4);
            bReg2 = *reinterpret_cast<const float4*>(wp + 8);
            bReg3 = *reinterpret_cast<const float4*>(wp + 12);
        }

#pragma unroll
        for (int k = 0; k < BK; k++) {
            float4 a0 = *reinterpret_cast<const float4*>(&As[k][ty * 4]);
            float4 a1 = *reinterpret_cast<const float4*>(&As[k][ty * 4 + 32]);
            float4 b0 = *reinterpret_cast<const float4*>(&Bs[k][tx * 4]);
            float4 b1 = *reinterpret_cast<const float4*>(&Bs[k][tx * 4 + 128]);

            // a row-pairs are already packed (little-endian float4 -> 2x f32x2)
            ull ap0 = reinterpret_cast<const ull*>(&a0)[0];  // rows ty*4+0, +1
            ull ap1 = reinterpret_cast<const ull*>(&a0)[1];  // rows ty*4+2, +3
            ull ap2 = reinterpret_cast<const ull*>(&a1)[0];  // rows ty*4+32,+33
            ull ap3 = reinterpret_cast<const ull*>(&a1)[1];  // rows ty*4+34,+35

            ull bb[8];
            bb[0] = pack2(b0.x, b0.x); bb[1] = pack2(b0.y, b0.y);
            bb[2] = pack2(b0.z, b0.z); bb[3] = pack2(b0.w, b0.w);
            bb[4] = pack2(b1.x, b1.x); bb[5] = pack2(b1.y, b1.y);
            bb[6] = pack2(b1.z, b1.z); bb[7] = pack2(b1.w, b1.w);

#pragma unroll
            for (int c = 0; c < 8; c++) {
                fma2(acc[0][c], ap0, bb[c]);
                fma2(acc[1][c], ap1, bb[c]);
                fma2(acc[2][c], ap2, bb[c]);
                fma2(acc[3][c], ap3, bb[c]);
            }
        }
    }

    // Writeback: each row-pair rp covers rows (rbase, rbase+1)
#pragma unroll
    for (int rp = 0; rp < 4; rp++) {
        const int rbase = ty * 4 + ((rp >> 1) * 32) + ((rp & 1) * 2);
        float2 u[8];
#pragma unroll
        for (int c = 0; c < 8; c++) u[c] = unpack2(acc[rp][c]);

        float4 lo0 = make_float4(u[0].x, u[1].x, u[2].x, u[3].x);
        float4 lo1 = make_float4(u[4].x, u[5].x, u[6].x, u[7].x);
        float4 hi0 = make_float4(u[0].y, u[1].y, u[2].y, u[3].y);
        float4 hi1 = make_float4(u[4].y, u[5].y, u[6].y, u[7].y);

        float* orow = g_logits + (size_t)(block_m + rbase) * NUM_EXPERTS;
        *reinterpret_cast<float4*>(&orow[tx * 4])       = lo0;
        *reinterpret_cast<float4*>(&orow[tx * 4 + 128]) = lo1;
        orow += NUM_EXPERTS;
        *reinterpret_cast<float4*>(&orow[tx * 4])       = hi0;
        *reinterpret_cast<float4*>(&orow[tx * 4 + 128]) = hi1;
    }
}

// ---------------------------------------------------------------------------
// Kernel 2: routing epilogue. One warp per token; lane handles 8 experts
// (lane*8 .. lane*8+7), so group g (32 experts) = lanes 4g..4g+3.
// Tie-breaks replicate jax.lax.top_k: lower index wins on equal values.
// ---------------------------------------------------------------------------
__global__ __launch_bounds__(256)
void gate_route_kernel(const float* __restrict__ bias, float* __restrict__ out) {
    const int lane  = threadIdx.x & 31;
    const int warp  = threadIdx.x >> 5;
    const int token = blockIdx.x * 8 + warp;

    const float* lrow = g_logits + (size_t)token * NUM_EXPERTS;
    const int ebase = lane * 8;

    float4 l0 = *reinterpret_cast<const float4*>(&lrow[ebase]);
    float4 l1 = *reinterpret_cast<const float4*>(&lrow[ebase + 4]);
    float4 c0 = *reinterpret_cast<const float4*>(&bias[ebase]);
    float4 c1 = *reinterpret_cast<const float4*>(&bias[ebase + 4]);

    float lg[8]  = {l0.x, l0.y, l0.z, l0.w, l1.x, l1.y, l1.z, l1.w};
    float bs[8]  = {c0.x, c0.y, c0.z, c0.w, c1.x, c1.y, c1.z, c1.w};

    float score[8], swb[8];
#pragma unroll
    for (int i = 0; i < 8; i++) {
        float x = lg[i];
        float s;
        if (x >= 0.0f) { float z = expf(-x); s = 1.0f / (1.0f + z); }
        else           { float z = expf(x);  s = z / (1.0f + z); }
        score[i] = s;
        swb[i]   = s + bs[i];
    }

    // Lane-local top-2 of biased scores
    float h1 = -INFINITY, h2 = -INFINITY;
#pragma unroll
    for (int i = 0; i < 8; i++) {
        float v = swb[i];
        if (v > h1) { h2 = h1; h1 = v; }
        else if (v > h2) { h2 = v; }
    }
    // Merge top-2 across the 4 lanes of each group (xor 1, 2 stay in-quad)
#pragma unroll
    for (int m = 1; m <= 2; m <<= 1) {
        float o1 = __shfl_xor_sync(0xffffffffu, h1, m);
        float o2 = __shfl_xor_sync(0xffffffffu, h2, m);
        float a = fmaxf(h1, o1);
        float b = fminf(h1, o1);
        float c = fmaxf(fmaxf(h2, o2), b);
        h1 = a; h2 = c;
    }
    float gscore = h1 + h2;   // valid in every lane of the quad

    float gs[8];
#pragma unroll
    for (int g = 0; g < 8; g++) gs[g] = __shfl_sync(0xffffffffu, gscore, g * 4);

    // Top-4 groups (strict > with ascending scan => lowest index wins ties)
    unsigned gmask = 0;
#pragma unroll
    for (int r = 0; r < 4; r++) {
        float best = -INFINITY; int bi = 0;
#pragma unroll
        for (int g = 0; g < 8; g++) {
            bool avail = !((gmask >> g) & 1u);
            if (avail && gs[g] > best) { best = gs[g]; bi = g; }
        }
        gmask |= 1u << bi;
    }

    const bool inmask = (gmask >> (lane >> 2)) & 1u;
    float mval[8];
#pragma unroll
    for (int i = 0; i < 8; i++) mval[i] = inmask ? swb[i] : 0.0f;

    // Top-8 experts over masked biased scores (value desc, index asc tiebreak)
    unsigned selbits = 0;
#pragma unroll
    for (int r = 0; r < 8; r++) {
        float bv = -INFINITY; int bidx = 0x3fffffff;
#pragma unroll
        for (int i = 0; i < 8; i++) {
            if (!((selbits >> i) & 1u)) {
                float v = mval[i]; int e = ebase + i;
                if (v > bv || (v == bv && e < bidx)) { bv = v; bidx = e; }
            }
        }
#pragma unroll
        for (int off = 16; off >= 1; off >>= 1) {
            float ov = __shfl_xor_sync(0xffffffffu, bv, off);
            int   oi = __shfl_xor_sync(0xffffffffu, bidx, off);
            if (ov > bv || (ov == bv && oi < bidx)) { bv = ov; bidx = oi; }
        }
        if ((bidx >> 3) == lane) selbits |= 1u << (bidx & 7);
    }

    // Renormalize selected raw sigmoid scores
    float d = 0.0f;
#pragma unroll
    for (int i = 0; i < 8; i++) if ((selbits >> i) & 1u) d += score[i];
#pragma unroll
    for (int off = 16; off >= 1; off >>= 1) d += __shfl_xor_sync(0xffffffffu, d, off);
    d += 1e-20f;

    float o[8];
#pragma unroll
    for (int i = 0; i < 8; i++)
        o[i] = ((selbits >> i) & 1u) ? (score[i] / d) * 2.5f : 0.0f;

    float* orow = out + (size_t)token * NUM_EXPERTS + ebase;
    *reinterpret_cast<float4*>(&orow[0]) = make_float4(o[0], o[1], o[2], o[3]);
    *reinterpret_cast<float4*>(&orow[4]) = make_float4(o[4], o[5], o[6], o[7]);
}

// ---------------------------------------------------------------------------
extern "C" void kernel_launch(void* const* d_in, const int* in_sizes, int n_in,
                              void* d_out, int out_size) {
    const float* hidden = (const float*)d_in[0];   // [16384, 7168] fp32
    const float* weight = (const float*)d_in[1];   // [256, 7168]  fp32
    const float* bias   = (const float*)d_in[2];   // [256]        fp32
    float* out = (float*)d_out;                    // [16384, 256] fp32

    gate_gemm_kernel<<<NUM_TOKENS / BM, NTHREADS>>>(hidden, weight);
    gate_route_kernel<<<NUM_TOKENS / 8, 256>>>(bias, out);
}

// round 8
// speedup vs baseline: 1.4243x; 1.4243x over previous
#include <cuda_runtime.h>
#include <cuda_bf16.h>
#include <cstdint>
#include <math.h>

#define NUM_TOKENS 16384
#define NUM_EXPERTS 256
#define HIDDEN     7168
#define M_TILE     128
#define KC         64
#define NCHUNKS    (HIDDEN / KC)          // 112
#define NTH        256

// Margin thresholds (score-space). 3-product GEMM score error ~1e-5 (5 sigma).
#define TAU_E 1e-4f
#define TAU_G 2e-4f

// Row stride in the bf16 tiles: 64 halves data + 8 halves pad = 144 bytes.
#define RSTRIDE      144
#define A_TILE_B     (M_TILE * RSTRIDE)        // 18432
#define W_TILE_B     (NUM_EXPERTS * RSTRIDE)   // 36864
#define OFF_AHI      0
#define OFF_ALO      A_TILE_B
#define OFF_WHI      (2 * A_TILE_B)
#define OFF_WLO      (OFF_WHI + W_TILE_B)
#define STAGE_B      (OFF_WLO + W_TILE_B)      // 110592
#define SMEM_TOTAL   (2 * STAGE_B)             // 221184

#define LSTRIDE_B    1056                      // 264 floats per logits row

typedef unsigned long long ull;

// W pre-converted to bf16 hi/lo, [NCHUNKS][256 rows][144 B] — same layout as smem.
__device__ uint8_t g_Whi[NCHUNKS * W_TILE_B];
__device__ uint8_t g_Wlo[NCHUNKS * W_TILE_B];

// Margin-triggered repair list
__device__ int g_fix_cnt;
__device__ int g_fix_list[NUM_TOKENS];

// ---------------- helpers ---------------------------------------------------
__device__ __forceinline__ uint32_t smem_u32(const void* p) {
    uint32_t a;
    asm("{ .reg .u64 t; cvta.to.shared.u64 t, %1; cvt.u32.u64 %0, t; }" : "=r"(a) : "l"(p));
    return a;
}
#define CP_ASYNC16(dst, src) \
    asm volatile("cp.async.cg.shared.global [%0], [%1], 16;" :: "r"((uint32_t)(dst)), "l"(src))
#define CP_COMMIT() asm volatile("cp.async.commit_group;" ::: "memory")
#define CP_WAIT0()  asm volatile("cp.async.wait_group 0;" ::: "memory")

__device__ __forceinline__ void sts8(uint32_t a, uint32_t x, uint32_t y) {
    asm volatile("st.shared.v2.b32 [%0], {%1, %2};" :: "r"(a), "r"(x), "r"(y));
}
__device__ __forceinline__ float4 lds16f(uint32_t a) {
    float4 v;
    asm volatile("ld.shared.v4.f32 {%0, %1, %2, %3}, [%4];"
                 : "=f"(v.x), "=f"(v.y), "=f"(v.z), "=f"(v.w) : "r"(a));
    return v;
}
__device__ __forceinline__ uint32_t packbf(__nv_bfloat16 a, __nv_bfloat16 b) {
    __nv_bfloat162 t; t.x = a; t.y = b;
    return *reinterpret_cast<uint32_t*>(&t);
}
__device__ __forceinline__ void ldm_x4(uint32_t* r, uint32_t addr) {
    asm volatile("ldmatrix.sync.aligned.m8n8.x4.shared.b16 {%0,%1,%2,%3}, [%4];"
                 : "=r"(r[0]), "=r"(r[1]), "=r"(r[2]), "=r"(r[3]) : "r"(addr));
}
__device__ __forceinline__ void mma16816(float* d, const uint32_t* a, const uint32_t* b) {
    asm volatile(
        "mma.sync.aligned.m16n8k16.row.col.f32.bf16.bf16.f32 "
        "{%0,%1,%2,%3}, {%4,%5,%6,%7}, {%8,%9}, {%0,%1,%2,%3};"
        : "+f"(d[0]), "+f"(d[1]), "+f"(d[2]), "+f"(d[3])
        : "r"(a[0]), "r"(a[1]), "r"(a[2]), "r"(a[3]), "r"(b[0]), "r"(b[1]));
}
__device__ __forceinline__ void fma2(ull& acc, ull a, ull b) {
    asm("fma.rn.f32x2 %0, %1, %2, %0;" : "+l"(acc) : "l"(a), "l"(b));
}
__device__ __forceinline__ ull pack2(float x, float y) {
    ull r; asm("mov.b64 %0, {%1, %2};" : "=l"(r) : "f"(x), "f"(y)); return r;
}
__device__ __forceinline__ float2 unpack2(ull v) {
    float2 f; asm("mov.b64 {%0, %1}, %2;" : "=f"(f.x), "=f"(f.y) : "l"(v)); return f;
}

// ---------------------------------------------------------------------------
// Kernel 0: W fp32 -> bf16 hi/lo, chunk-tiled, stride-144 (== smem layout)
// Also zeroes the repair counter each launch.
// ---------------------------------------------------------------------------
__global__ __launch_bounds__(256)
void convert_w_kernel(const float* __restrict__ W) {
    if (blockIdx.x == 0 && threadIdx.x == 0) g_fix_cnt = 0;

    const int K4 = HIDDEN / 4;                          // 1792
    size_t tix = (size_t)blockIdx.x * 256 + threadIdx.x;
    int n = (int)(tix / K4);
    int k = (int)(tix % K4) * 4;
    float4 v = *reinterpret_cast<const float4*>(W + (size_t)n * HIDDEN + k);

    __nv_bfloat16 hx = __float2bfloat16_rn(v.x);
    __nv_bfloat16 hy = __float2bfloat16_rn(v.y);
    __nv_bfloat16 hz = __float2bfloat16_rn(v.z);
    __nv_bfloat16 hw = __float2bfloat16_rn(v.w);
    __nv_bfloat16 lx = __float2bfloat16_rn(v.x - __bfloat162float(hx));
    __nv_bfloat16 ly = __float2bfloat16_rn(v.y - __bfloat162float(hy));
    __nv_bfloat16 lz = __float2bfloat16_rn(v.z - __bfloat162float(hz));
    __nv_bfloat16 lw = __float2bfloat16_rn(v.w - __bfloat162float(hw));

    int chunk = k >> 6;
    int kc    = k & 63;
    size_t base = (size_t)chunk * W_TILE_B + (size_t)n * RSTRIDE + kc * 2;
    *reinterpret_cast<uint2*>(g_Whi + base) = make_uint2(packbf(hx, hy), packbf(hz, hw));
    *reinterpret_cast<uint2*>(g_Wlo + base) = make_uint2(packbf(lx, ly), packbf(lz, lw));
}

// ---------------------------------------------------------------------------
// Routing (round-1 verified math) + decision margins. One warp = 1 token.
// margin_g: 4th-vs-5th group score gap; margin_e: 8th-vs-9th expert gap.
// ---------------------------------------------------------------------------
__device__ __forceinline__ void route_token(const float lg[8], const float bs[8],
                                            float* __restrict__ orow, int lane,
                                            float& margin_g, float& margin_e) {
    float score[8], swb[8];
#pragma unroll
    for (int i = 0; i < 8; i++) {
        float x = lg[i];
        float s;
        if (x >= 0.0f) { float z = expf(-x); s = 1.0f / (1.0f + z); }
        else           { float z = expf(x);  s = z / (1.0f + z); }
        score[i] = s;
        swb[i]   = s + bs[i];
    }

    float h1 = -INFINITY, h2 = -INFINITY;
#pragma unroll
    for (int i = 0; i < 8; i++) {
        float v = swb[i];
        if (v > h1) { h2 = h1; h1 = v; }
        else if (v > h2) { h2 = v; }
    }
#pragma unroll
    for (int m = 1; m <= 2; m <<= 1) {
        float o1 = __shfl_xor_sync(0xffffffffu, h1, m);
        float o2 = __shfl_xor_sync(0xffffffffu, h2, m);
        float a = fmaxf(h1, o1);
        float b = fminf(h1, o1);
        float c = fmaxf(fmaxf(h2, o2), b);
        h1 = a; h2 = c;
    }
    float gscore = h1 + h2;

    float gs[8];
#pragma unroll
    for (int g = 0; g < 8; g++) gs[g] = __shfl_sync(0xffffffffu, gscore, g * 4);

    // Top-4 groups + 5th for margin
    unsigned gmask = 0;
    float val4 = 0.0f, val5 = 0.0f;
#pragma unroll
    for (int r = 0; r < 5; r++) {
        float best = -INFINITY; int bi = 0;
#pragma unroll
        for (int g = 0; g < 8; g++) {
            bool avail = !((gmask >> g) & 1u);
            if (avail && gs[g] > best) { best = gs[g]; bi = g; }
        }
        if (r < 4) { gmask |= 1u << bi; val4 = best; }
        else       { val5 = best; }
    }
    margin_g = val4 - val5;

    const bool inmask = (gmask >> (lane >> 2)) & 1u;
    const int ebase = lane * 8;
    float mval[8];
#pragma unroll
    for (int i = 0; i < 8; i++) mval[i] = inmask ? swb[i] : 0.0f;

    // Top-8 experts + 9th for margin
    unsigned selbits = 0;
    float v8 = 0.0f, v9 = 0.0f;
#pragma unroll
    for (int r = 0; r < 9; r++) {
        float bv = -INFINITY; int bidx = 0x3fffffff;
#pragma unroll
        for (int i = 0; i < 8; i++) {
            if (!((selbits >> i) & 1u)) {
                float v = mval[i]; int e = ebase + i;
                if (v > bv || (v == bv && e < bidx)) { bv = v; bidx = e; }
            }
        }
#pragma unroll
        for (int off = 16; off >= 1; off >>= 1) {
            float ov = __shfl_xor_sync(0xffffffffu, bv, off);
            int   oi = __shfl_xor_sync(0xffffffffu, bidx, off);
            if (ov > bv || (ov == bv && oi < bidx)) { bv = ov; bidx = oi; }
        }
        if (r < 8) {
            if ((bidx >> 3) == lane) selbits |= 1u << (bidx & 7);
            if (r == 7) v8 = bv;
        } else v9 = bv;
    }
    margin_e = v8 - v9;

    float d = 0.0f;
#pragma unroll
    for (int i = 0; i < 8; i++) if ((selbits >> i) & 1u) d += score[i];
#pragma unroll
    for (int off = 16; off >= 1; off >>= 1) d += __shfl_xor_sync(0xffffffffu, d, off);
    d += 1e-20f;

    float o[8];
#pragma unroll
    for (int i = 0; i < 8; i++)
        o[i] = ((selbits >> i) & 1u) ? (score[i] / d) * 2.5f : 0.0f;

    *reinterpret_cast<float4*>(&orow[ebase])     = make_float4(o[0], o[1], o[2], o[3]);
    *reinterpret_cast<float4*>(&orow[ebase + 4]) = make_float4(o[4], o[5], o[6], o[7]);
}

// ---------------------------------------------------------------------------
// Kernel 1: fused gate GEMM (3-product split bf16 mma.sync) + routing + triggers
// ---------------------------------------------------------------------------
__global__ __launch_bounds__(NTH, 1)
void gate_fused_kernel(const float* __restrict__ A, const float* __restrict__ bias,
                       float* __restrict__ out) {
    extern __shared__ char smem[];
    const uint32_t sb = smem_u32(smem);
    const int tid  = threadIdx.x;
    const int lane = tid & 31;
    const int w    = tid >> 5;
    const int wm   = w >> 2;
    const int wn   = w & 3;
    const int m0   = blockIdx.x * M_TILE;

    float4 bv0 = *reinterpret_cast<const float4*>(bias + lane * 8);
    float4 bv1 = *reinterpret_cast<const float4*>(bias + lane * 8 + 4);

    const int arow = tid >> 1;
    const int ahalf = tid & 1;
    const float* abase_g = A + (size_t)(m0 + arow) * HIDDEN + ahalf * 32;
    const uint32_t asts_base = (uint32_t)(arow * RSTRIDE + ahalf * 64);

    float4 areg[8];
    auto LDA = [&](int it) {
        const float4* p = reinterpret_cast<const float4*>(abase_g + it * KC);
#pragma unroll
        for (int j = 0; j < 8; j++) areg[j] = p[j];
    };
    auto STA = [&](uint32_t buf) {
        const uint32_t hb = buf + OFF_AHI + asts_base;
        const uint32_t lb = buf + OFF_ALO + asts_base;
#pragma unroll
        for (int j = 0; j < 8; j++) {
            float4 v = areg[j];
            __nv_bfloat16 hx = __float2bfloat16_rn(v.x);
            __nv_bfloat16 hy = __float2bfloat16_rn(v.y);
            __nv_bfloat16 hz = __float2bfloat16_rn(v.z);
            __nv_bfloat16 hw = __float2bfloat16_rn(v.w);
            sts8(hb + 8 * j, packbf(hx, hy), packbf(hz, hw));
            __nv_bfloat16 lx = __float2bfloat16_rn(v.x - __bfloat162float(hx));
            __nv_bfloat16 ly = __float2bfloat16_rn(v.y - __bfloat162float(hy));
            __nv_bfloat16 lz = __float2bfloat16_rn(v.z - __bfloat162float(hz));
            __nv_bfloat16 lw = __float2bfloat16_rn(v.w - __bfloat162float(hw));
            sts8(lb + 8 * j, packbf(lx, ly), packbf(lz, lw));
        }
    };
    auto CPW = [&](int it, uint32_t buf) {
        const uint8_t* wh = g_Whi + (size_t)it * W_TILE_B;
        const uint8_t* wl = g_Wlo + (size_t)it * W_TILE_B;
#pragma unroll
        for (int i = 0; i < 9; i++) {
            uint32_t off = (uint32_t)(i * 256 + tid) * 16;
            CP_ASYNC16(buf + OFF_WHI + off, wh + off);
            CP_ASYNC16(buf + OFF_WLO + off, wl + off);
        }
    };

    const uint32_t a_lane = (uint32_t)((lane & 15) * RSTRIDE + (lane >> 4) * 16);
    const uint32_t b_lane = (uint32_t)(((lane & 7) + ((lane >> 4) & 1) * 8) * RSTRIDE
                                       + ((lane >> 3) & 1) * 16);

    float acc[4][8][4];
#pragma unroll
    for (int mi = 0; mi < 4; mi++)
#pragma unroll
        for (int ni = 0; ni < 8; ni++)
#pragma unroll
            for (int q = 0; q < 4; q++) acc[mi][ni][q] = 0.0f;

    {
        CPW(0, sb); CP_COMMIT();
        LDA(0); STA(sb);
        CP_WAIT0();
        __syncthreads();
    }

    const uint32_t am_base = (uint32_t)(wm * 64 * RSTRIDE);
    const uint32_t bn_base = (uint32_t)(wn * 64 * RSTRIDE);

    for (int it = 0; it < NCHUNKS; it++) {
        const uint32_t cur = sb + (uint32_t)(it & 1) * STAGE_B;
        const uint32_t nxt = sb + (uint32_t)((it + 1) & 1) * STAGE_B;

        if (it + 1 < NCHUNKS) {
            CPW(it + 1, nxt); CP_COMMIT();
            LDA(it + 1);
        }

#pragma unroll
        for (int ks = 0; ks < 4; ks++) {
            const uint32_t kb = (uint32_t)ks * 32;
#pragma unroll
            for (int p = 0; p < 3; p++) {
                const uint32_t ab = cur + (p == 2 ? OFF_ALO : OFF_AHI) + am_base + kb + a_lane;
                const uint32_t bb = cur + (p == 1 ? OFF_WLO : OFF_WHI) + bn_base + kb + b_lane;
                uint32_t af[16], bf[16];
#pragma unroll
                for (int mi = 0; mi < 4; mi++) ldm_x4(af + mi * 4, ab + mi * 16 * RSTRIDE);
#pragma unroll
                for (int q = 0; q < 4; q++)    ldm_x4(bf + q  * 4, bb + q  * 16 * RSTRIDE);
#pragma unroll
                for (int mi = 0; mi < 4; mi++)
#pragma unroll
                    for (int ni = 0; ni < 8; ni++)
                        mma16816(acc[mi][ni], af + mi * 4, bf + (ni >> 1) * 4 + (ni & 1) * 2);
            }
        }

        if (it + 1 < NCHUNKS) STA(nxt);
        CP_WAIT0();
        __syncthreads();
    }

    // ---- epilogue: accum frags -> smem logits
    {
        const int gid = lane >> 2;
        const int tig = lane & 3;
#pragma unroll
        for (int mi = 0; mi < 4; mi++) {
#pragma unroll
            for (int ni = 0; ni < 8; ni++) {
                const int col = wn * 64 + ni * 8 + tig * 2;
                const int r0 = wm * 64 + mi * 16 + gid;
                uint32_t a0 = sb + (uint32_t)r0 * LSTRIDE_B + col * 4;
                sts8(a0, __float_as_uint(acc[mi][ni][0]), __float_as_uint(acc[mi][ni][1]));
                sts8(a0 + 8u * LSTRIDE_B, __float_as_uint(acc[mi][ni][2]),
                                          __float_as_uint(acc[mi][ni][3]));
            }
        }
    }
    __syncthreads();

    // ---- fused routing + margin triggers
    {
        const float bs[8] = {bv0.x, bv0.y, bv0.z, bv0.w, bv1.x, bv1.y, bv1.z, bv1.w};
        for (int i = 0; i < 16; i++) {
            const int t = w * 16 + i;
            const uint32_t src = sb + (uint32_t)t * LSTRIDE_B + lane * 32;
            float4 l0 = lds16f(src);
            float4 l1 = lds16f(src + 16);
            const float lg[8] = {l0.x, l0.y, l0.z, l0.w, l1.x, l1.y, l1.z, l1.w};
            float mg, me;
            route_token(lg, bs, out + (size_t)(m0 + t) * NUM_EXPERTS, lane, mg, me);
            if (lane == 0 && (mg < TAU_G || me < TAU_E)) {
                int p = atomicAdd(&g_fix_cnt, 1);
                if (p < NUM_TOKENS) g_fix_list[p] = m0 + t;
            }
        }
    }
}

// ---------------------------------------------------------------------------
// Kernel 2: exact fp32 repair of marginal tokens. 4 tokens per block-chunk.
// thread = expert; A rows staged in smem; f32x2 accumulate (4 partials/token).
// ---------------------------------------------------------------------------
__global__ __launch_bounds__(256)
void repair_kernel(const float* __restrict__ A, const float* __restrict__ W,
                   const float* __restrict__ bias, float* __restrict__ out) {
    __shared__ float sA[4][1024];
    __shared__ float sLog[4][264];

    const int tid  = threadIdx.x;
    const int lane = tid & 31;
    const int w    = tid >> 5;
    const int cnt  = g_fix_cnt;

    float4 bv0 = *reinterpret_cast<const float4*>(bias + lane * 8);
    float4 bv1 = *reinterpret_cast<const float4*>(bias + lane * 8 + 4);
    const float bs[8] = {bv0.x, bv0.y, bv0.z, bv0.w, bv1.x, bv1.y, bv1.z, bv1.w};

    const float* wrow = W + (size_t)tid * HIDDEN;

    for (int base = blockIdx.x * 4; base < cnt; base += gridDim.x * 4) {
        int tk[4];
#pragma unroll
        for (int i = 0; i < 4; i++) {
            int idx = base + i;
            tk[i] = g_fix_list[idx < cnt ? idx : cnt - 1];
        }

        ull acc[4][2];
#pragma unroll
        for (int t = 0; t < 4; t++) { acc[t][0] = 0ull; acc[t][1] = 0ull; }

        for (int kt = 0; kt < 7; kt++) {
            __syncthreads();
#pragma unroll
            for (int j = 0; j < 4; j++) {
                int idx = j * 256 + tid;         // 0..1023
                int t  = idx >> 8;
                int k4 = (idx & 255) * 4;
                *reinterpret_cast<float4*>(&sA[t][k4]) =
                    *reinterpret_cast<const float4*>(A + (size_t)tk[t] * HIDDEN + kt * 1024 + k4);
            }
            __syncthreads();

            const float4* wp = reinterpret_cast<const float4*>(wrow + kt * 1024);
#pragma unroll 4
            for (int k4 = 0; k4 < 256; k4++) {
                float4 wv = wp[k4];
                ull wxy = pack2(wv.x, wv.y);
                ull wzw = pack2(wv.z, wv.w);
#pragma unroll
                for (int t = 0; t < 4; t++) {
                    const ull* av = reinterpret_cast<const ull*>(&sA[t][k4 * 4]);
                    fma2(acc[t][0], av[0], wxy);
                    fma2(acc[t][1], av[1], wzw);
                }
            }
        }

#pragma unroll
        for (int t = 0; t < 4; t++) {
            float2 u0 = unpack2(acc[t][0]);
            float2 u1 = unpack2(acc[t][1]);
            sLog[t][tid] = (u0.x + u1.x) + (u0.y + u1.y);
        }
        __syncthreads();

        // warps 0-3 route one token each (warps 4-7 idle this part)
        if (w < 4) {
            float4 l0 = *reinterpret_cast<const float4*>(&sLog[w][lane * 8]);
            float4 l1 = *reinterpret_cast<const float4*>(&sLog[w][lane * 8 + 4]);
            const float lg[8] = {l0.x, l0.y, l0.z, l0.w, l1.x, l1.y, l1.z, l1.w};
            float mg, me;
            route_token(lg, bs, out + (size_t)tk[w] * NUM_EXPERTS, lane, mg, me);
        }
        __syncthreads();
    }
}

// ---------------------------------------------------------------------------
extern "C" void kernel_launch(void* const* d_in, const int* in_sizes, int n_in,
                              void* d_out, int out_size) {
    const float* hidden = (const float*)d_in[0];   // [16384, 7168]
    const float* weight = (const float*)d_in[1];   // [256, 7168]
    const float* bias   = (const float*)d_in[2];   // [256]
    float* out = (float*)d_out;                    // [16384, 256]

    convert_w_kernel<<<(NUM_EXPERTS * HIDDEN / 4) / 256, 256>>>(weight);

    cudaFuncSetAttribute(gate_fused_kernel,
                         cudaFuncAttributeMaxDynamicSharedMemorySize, SMEM_TOTAL);
    gate_fused_kernel<<<NUM_TOKENS / M_TILE, NTH, SMEM_TOTAL>>>(hidden, bias, out);

    repair_kernel<<<128, 256>>>(hidden, weight, bias, out);
}